// round 2
// baseline (speedup 1.0000x reference)
#include <cuda_runtime.h>
#include <math.h>

#define N_TOK 2048
#define DMODEL 512
#define NH 8
#define DH 64
#define FF 2
#define HH 32
#define WW 32

// Scratch (device globals; no allocations allowed)
__device__ float g_qkv[N_TOK * 3 * DMODEL];   // [t][q(512) | k(512) | v(512)]
__device__ float g_ah[N_TOK * DMODEL];        // attention output (pre out-proj)

// ---------------------------------------------------------------------------
// QKV GEMM: g_qkv[2048,1536] = x[2048,512] @ w_qkv[512,1536]
// BM=128, BN=64, BK=16, 256 threads, thread tile 8x4
// ---------------------------------------------------------------------------
__global__ void qkv_gemm_kernel(const float* __restrict__ A,
                                const float* __restrict__ B) {
    const int M = N_TOK, N = 3 * DMODEL, K = DMODEL;
    __shared__ float As[16][128];
    __shared__ float Bs[16][64];
    int tid = threadIdx.x;
    int tx = tid & 15, ty = tid >> 4;
    int row0 = blockIdx.y * 128;
    int col0 = blockIdx.x * 64;
    float acc[8][4] = {};
    for (int k0 = 0; k0 < K; k0 += 16) {
#pragma unroll
        for (int i = 0; i < 2; i++) {
            int id = tid + i * 256;            // 0..511 float4s of A tile (128x16)
            int r = id >> 2, cv = (id & 3) << 2;
            const float4 v = *(const float4*)&A[(size_t)(row0 + r) * K + k0 + cv];
            As[cv + 0][r] = v.x; As[cv + 1][r] = v.y;
            As[cv + 2][r] = v.z; As[cv + 3][r] = v.w;
        }
        {
            int r = tid >> 4, cv = (tid & 15) << 2;  // B tile 16x64
            *(float4*)&Bs[r][cv] =
                *(const float4*)&B[(size_t)(k0 + r) * N + col0 + cv];
        }
        __syncthreads();
#pragma unroll
        for (int k = 0; k < 16; k++) {
            float a[8], b[4];
#pragma unroll
            for (int j = 0; j < 4; j++) b[j] = Bs[k][tx * 4 + j];
#pragma unroll
            for (int i = 0; i < 8; i++) a[i] = As[k][ty * 8 + i];
#pragma unroll
            for (int i = 0; i < 8; i++)
#pragma unroll
                for (int j = 0; j < 4; j++)
                    acc[i][j] = fmaf(a[i], b[j], acc[i][j]);
        }
        __syncthreads();
    }
#pragma unroll
    for (int i = 0; i < 8; i++) {
        float4 v;
        v.x = acc[i][0]; v.y = acc[i][1]; v.z = acc[i][2]; v.w = acc[i][3];
        *(float4*)&g_qkv[(size_t)(row0 + ty * 8 + i) * N + col0 + tx * 4] = v;
    }
}

// ---------------------------------------------------------------------------
// Attention: one block per (W-row of 32 queries, head). 256 threads,
// 8 threads per query (each owns 8 dims). Online softmax over BOS + 125 slots.
// For each (df,dh) of the 5x5x5 window, the 5 dw slots of all 32 queries
// come from one contiguous 32-token chunk -> staged in smem (transposed).
// ---------------------------------------------------------------------------
__global__ void attn_kernel() {
    const float* __restrict__ qkv = g_qkv;
    int r = blockIdx.x;            // 0..63 : row in i-space (f*32 + h)
    int h = blockIdx.y;            // head
    int f = r >> 5;
    int hp = r & 31;
    int i0 = r * 32;
    int tid = threadIdx.x;
    int ql = tid >> 3;             // query within block = w coordinate (0..31)
    int g  = tid & 7;              // dim-group (owns dims g*8 .. g*8+7)
    int hoff = h * DH;

    __shared__ float Ks[64][33];   // [d][c], padded
    __shared__ float Vs[64][33];

    int iq = i0 + ql;              // query index i
    int t  = iq + 1;               // output token (q uses x[t])
    const float scale = 0.125f;    // 64^-0.5

    float q[8];
    if (t < N_TOK) {
#pragma unroll
        for (int d = 0; d < 8; d++)
            q[d] = qkv[(size_t)t * 1536 + hoff + g * 8 + d] * scale;
    } else {
#pragma unroll
        for (int d = 0; d < 8; d++) q[d] = 0.f;
    }

    // --- BOS slot (always attended): K/V of token 0 ---
    float m, l, acc[8];
    {
        float s = 0.f;
#pragma unroll
        for (int d = 0; d < 8; d++)
            s += q[d] * qkv[512 + hoff + g * 8 + d];
        s += __shfl_xor_sync(0xffffffffu, s, 1);
        s += __shfl_xor_sync(0xffffffffu, s, 2);
        s += __shfl_xor_sync(0xffffffffu, s, 4);
        m = s; l = 1.f;
#pragma unroll
        for (int d = 0; d < 8; d++)
            acc[d] = qkv[1024 + hoff + g * 8 + d];
    }

    for (int df = -2; df <= 2; df++) {
        int nf = f + df;
        if (nf < 0 || nf >= FF) continue;
        for (int dh = -2; dh <= 2; dh++) {
            int nh = hp + dh;
            if (nh < 0 || nh >= HH) continue;
            int j0 = (nf * HH + nh) * WW;

            __syncthreads();       // protect previous chunk reads
#pragma unroll
            for (int i = 0; i < 2; i++) {
                int id4 = tid + i * 256;     // 512 float4s over 32x64
                int c  = id4 >> 4;
                int dv = (id4 & 15) << 2;
                int tok = j0 + 1 + c;        // key token = neighbor j + 1
                float4 kk, vv;
                if (tok < N_TOK) {
                    kk = *(const float4*)&qkv[(size_t)tok * 1536 + 512 + hoff + dv];
                    vv = *(const float4*)&qkv[(size_t)tok * 1536 + 1024 + hoff + dv];
                } else {
                    kk = make_float4(0.f, 0.f, 0.f, 0.f);
                    vv = kk;
                }
                Ks[dv + 0][c] = kk.x; Ks[dv + 1][c] = kk.y;
                Ks[dv + 2][c] = kk.z; Ks[dv + 3][c] = kk.w;
                Vs[dv + 0][c] = vv.x; Vs[dv + 1][c] = vv.y;
                Vs[dv + 2][c] = vv.z; Vs[dv + 3][c] = vv.w;
            }
            __syncthreads();

#pragma unroll
            for (int dw = -2; dw <= 2; dw++) {
                int c = ql + dw;
                int j = j0 + c;
                bool valid = ((unsigned)c < 32u) && (j <= iq);  // causal
                int cc = min(max(c, 0), 31);
                float s = 0.f;
#pragma unroll
                for (int d = 0; d < 8; d++)
                    s += q[d] * Ks[g * 8 + d][cc];
                s += __shfl_xor_sync(0xffffffffu, s, 1);
                s += __shfl_xor_sync(0xffffffffu, s, 2);
                s += __shfl_xor_sync(0xffffffffu, s, 4);
                if (valid) {
                    float mn = fmaxf(m, s);
                    float corr = __expf(m - mn);
                    float p = __expf(s - mn);
                    l = l * corr + p;
#pragma unroll
                    for (int d = 0; d < 8; d++)
                        acc[d] = acc[d] * corr + p * Vs[g * 8 + d][cc];
                    m = mn;
                }
            }
        }
    }

    if (t < N_TOK) {
        float inv = 1.f / l;
#pragma unroll
        for (int d = 0; d < 8; d++)
            g_ah[(size_t)t * DMODEL + hoff + g * 8 + d] = acc[d] * inv;
    }
}

// Output row 0 is just V of token 0 (BOS passthrough)
__global__ void bos_kernel() {
    int d = threadIdx.x;           // 512 threads
    g_ah[d] = g_qkv[1024 + d];
}

// ---------------------------------------------------------------------------
// Out GEMM: out[2048,512] = g_ah[2048,512] @ w_out[512,512] + b_out
// BM=BN=64, BK=16, 256 threads, thread tile 4x4 -> 256 blocks (grid balance)
// ---------------------------------------------------------------------------
__global__ void out_gemm_kernel(const float* __restrict__ B,
                                const float* __restrict__ bias,
                                float* __restrict__ C) {
    const int M = N_TOK, N = DMODEL, K = DMODEL;
    const float* __restrict__ A = g_ah;
    __shared__ float As[16][64];
    __shared__ float Bs[16][64];
    int tid = threadIdx.x;
    int tx = tid & 15, ty = tid >> 4;
    int row0 = blockIdx.y * 64;
    int col0 = blockIdx.x * 64;
    float acc[4][4] = {};
    for (int k0 = 0; k0 < K; k0 += 16) {
        {
            int r = tid >> 2, cv = (tid & 3) << 2;      // A tile 64x16
            const float4 v = *(const float4*)&A[(size_t)(row0 + r) * K + k0 + cv];
            As[cv + 0][r] = v.x; As[cv + 1][r] = v.y;
            As[cv + 2][r] = v.z; As[cv + 3][r] = v.w;
        }
        {
            int r = tid >> 4, cv = (tid & 15) << 2;     // B tile 16x64
            *(float4*)&Bs[r][cv] =
                *(const float4*)&B[(size_t)(k0 + r) * N + col0 + cv];
        }
        __syncthreads();
#pragma unroll
        for (int k = 0; k < 16; k++) {
            float a[4], b[4];
#pragma unroll
            for (int j = 0; j < 4; j++) b[j] = Bs[k][tx * 4 + j];
#pragma unroll
            for (int i = 0; i < 4; i++) a[i] = As[k][ty * 4 + i];
#pragma unroll
            for (int i = 0; i < 4; i++)
#pragma unroll
                for (int j = 0; j < 4; j++)
                    acc[i][j] = fmaf(a[i], b[j], acc[i][j]);
        }
        __syncthreads();
    }
    float bb[4];
#pragma unroll
    for (int j = 0; j < 4; j++) bb[j] = bias[col0 + tx * 4 + j];
#pragma unroll
    for (int i = 0; i < 4; i++) {
        float4 v;
        v.x = acc[i][0] + bb[0]; v.y = acc[i][1] + bb[1];
        v.z = acc[i][2] + bb[2]; v.w = acc[i][3] + bb[3];
        *(float4*)&C[(size_t)(row0 + ty * 4 + i) * N + col0 + tx * 4] = v;
    }
}

extern "C" void kernel_launch(void* const* d_in, const int* in_sizes, int n_in,
                              void* d_out, int out_size) {
    const float* x     = (const float*)d_in[0];   // [1,2048,512]
    const float* w_qkv = (const float*)d_in[1];   // [512,1536]
    const float* w_out = (const float*)d_in[2];   // [512,512]
    const float* b_out = (const float*)d_in[3];   // [512]
    float* out = (float*)d_out;                   // [1,2048,512]

    qkv_gemm_kernel<<<dim3(1536 / 64, N_TOK / 128), 256>>>(x, w_qkv);
    attn_kernel<<<dim3(64, NH), 256>>>();
    bos_kernel<<<1, 512>>>();
    out_gemm_kernel<<<dim3(DMODEL / 64, N_TOK / 64), 256>>>(w_out, b_out, out);
}